// round 8
// baseline (speedup 1.0000x reference)
#include <cuda_runtime.h>
#include <cstdint>

#define B_    8
#define L_    768
#define H_    16
#define DK_   64
#define D_    1024
#define BH_   128
#define M_    6144
#define SCALE 0.125f

// Scratch (device globals; allocation forbidden)
__device__ float g_Xr[M_ * D_];                        // tf32-rounded input X
__device__ float g_Wq[D_ * D_], g_Wk[D_ * D_], g_Wv[D_ * D_], g_Wo[D_ * D_];
__device__ float g_Qp[BH_ * L_ * DK_];                 // [bh][l][dk] tf32
__device__ float g_Kp[BH_ * L_ * DK_];                 // tf32
__device__ float g_Vt[BH_ * DK_ * L_];                 // V^T [bh][dk][l] tf32
__device__ float g_Ec[1535 * 64];                      // tf32 rel embedding
__device__ float g_S [(size_t)BH_ * L_ * L_];          // unnormalized probs (tf32)
__device__ float g_InvSum[BH_ * L_];                   // 1/rowsum
__device__ float g_O2[(size_t)M_ * D_];                // attn out, merged, tf32

__device__ __forceinline__ float to_tf32(float x) {
    float r;
    asm("cvt.rna.tf32.f32 %0, %1;" : "=f"(r) : "f"(x));
    return r;
}
__device__ __forceinline__ uint32_t smem_u32(const void* p) {
    uint32_t a;
    asm("{ .reg .u64 t; cvta.to.shared.u64 t, %1; cvt.u32.u64 %0, t; }"
        : "=r"(a) : "l"(p));
    return a;
}
__device__ __forceinline__ void mma_tf32(float* d, const uint32_t* a, const uint32_t* b) {
    asm volatile(
        "mma.sync.aligned.m16n8k8.row.col.f32.tf32.tf32.f32 "
        "{%0,%1,%2,%3}, {%4,%5,%6,%7}, {%8,%9}, {%0,%1,%2,%3};"
        : "+f"(d[0]), "+f"(d[1]), "+f"(d[2]), "+f"(d[3])
        : "r"(a[0]), "r"(a[1]), "r"(a[2]), "r"(a[3]), "r"(b[0]), "r"(b[1]));
}
#define CP_A16(dst, src) \
    asm volatile("cp.async.ca.shared.global [%0], [%1], 16;" :: "r"(dst), "l"(src) : "memory")
#define CP_A16Z(dst, src, sz) \
    asm volatile("cp.async.ca.shared.global [%0], [%1], 16, %2;" :: "r"(dst), "l"(src), "r"(sz) : "memory")
#define CP_COMMIT() asm volatile("cp.async.commit_group;" ::: "memory")
#define CP_WAIT2()  asm volatile("cp.async.wait_group 2;" ::: "memory")
#define CP_WAIT1()  asm volatile("cp.async.wait_group 1;" ::: "memory")
#define CP_WAIT0()  asm volatile("cp.async.wait_group 0;" ::: "memory")

// ---------------------------------------------------------------------------
// tf32 pre-round
// ---------------------------------------------------------------------------
__global__ __launch_bounds__(256)
void conv_tf32(const float4* __restrict__ in, float4* __restrict__ out, int n4)
{
    int i = blockIdx.x * 256 + threadIdx.x;
    if (i < n4) {
        float4 v = in[i];
        out[i] = make_float4(to_tf32(v.x), to_tf32(v.y), to_tf32(v.z), to_tf32(v.w));
    }
}

// ---------------------------------------------------------------------------
// Projection GEMM: C[128,256] per CTA = A[128,1024] @ B[256,1024]^T.
// BK=16, 3-stage cp.async (2 outstanding), stride-20 smem (bank-free).
// 8 warps 2m x 4n; warp tile 64x64 (LDS:MMA = 1:1 per k-step).
// MODE 0: Q/K proj (head-split, tf32)  MODE 1: V proj (g_Vt^T, tf32)
// MODE 2: out proj (plain fp32)
// ---------------------------------------------------------------------------
template<int MODE>
__global__ __launch_bounds__(256)
void proj_mma(const float* __restrict__ Ag, const float* __restrict__ Bg,
              const float* __restrict__ bias, float* __restrict__ OUT)
{
    extern __shared__ float sm[];
    const uint32_t smb = smem_u32(sm);
    constexpr int STG = (128 + 256) * 20;    // floats per stage
    constexpr int NT  = 1024 / 16;           // 64 K-tiles

    const int tid = threadIdx.x, lane = tid & 31, wid = tid >> 5;
    const int g4 = lane >> 2, cq = lane & 3;
    const int wm = (wid & 1) * 64, wn = (wid >> 1) * 64;

    const float* Arow = Ag + (size_t)(blockIdx.y * 128) * 1024;
    const float* Brow = Bg + (size_t)(blockIdx.x * 256) * 1024;

    auto loadAB = [&](int t, int s) {
        const uint32_t base = smb + (uint32_t)s * STG * 4;
        const int k0 = t * 16;
#pragma unroll
        for (int i = 0; i < 2; ++i) {
            int idx = tid + i * 256;
            int r = idx >> 2, seg = (idx & 3) * 4;
            CP_A16(base + (uint32_t)(r * 20 + seg) * 4,
                   Arow + (size_t)r * 1024 + k0 + seg);
        }
#pragma unroll
        for (int i = 0; i < 4; ++i) {
            int idx = tid + i * 256;
            int r = idx >> 2, seg = (idx & 3) * 4;
            CP_A16(base + (uint32_t)(128 * 20 + r * 20 + seg) * 4,
                   Brow + (size_t)r * 1024 + k0 + seg);
        }
    };

    float acc[4][8][4] = {};

    loadAB(0, 0); CP_COMMIT();
    loadAB(1, 1); CP_COMMIT();

    for (int t = 0; t < NT; ++t) {
        if (t < NT - 1) { CP_WAIT1(); } else { CP_WAIT0(); }
        __syncthreads();
        if (t + 2 < NT) { loadAB(t + 2, (t + 2) % 3); CP_COMMIT(); }

        const float* As = sm + (t % 3) * STG;
        const float* Bs = As + 128 * 20;
#pragma unroll
        for (int ks = 0; ks < 2; ++ks) {
            uint32_t afr[4][4], bfr[8][2];
#pragma unroll
            for (int m = 0; m < 4; ++m) {
                const float* p = As + (wm + m * 16 + g4) * 20 + ks * 8 + cq;
                afr[m][0] = __float_as_uint(p[0]);
                afr[m][1] = __float_as_uint(p[8 * 20]);
                afr[m][2] = __float_as_uint(p[4]);
                afr[m][3] = __float_as_uint(p[8 * 20 + 4]);
            }
#pragma unroll
            for (int n = 0; n < 8; ++n) {
                const float* p = Bs + (wn + n * 8 + g4) * 20 + ks * 8 + cq;
                bfr[n][0] = __float_as_uint(p[0]);
                bfr[n][1] = __float_as_uint(p[4]);
            }
#pragma unroll
            for (int m = 0; m < 4; ++m)
#pragma unroll
                for (int n = 0; n < 8; ++n)
                    mma_tf32(acc[m][n], afr[m], bfr[n]);
        }
    }

#pragma unroll
    for (int m = 0; m < 4; ++m) {
#pragma unroll
        for (int n = 0; n < 8; ++n) {
            const int col = wn + n * 8 + cq * 2;
#pragma unroll
            for (int h2 = 0; h2 < 2; ++h2) {
                const int row = wm + m * 16 + g4 + h2 * 8;
                const float c0 = acc[m][n][h2 * 2 + 0];
                const float c1 = acc[m][n][h2 * 2 + 1];
                const int mg = blockIdx.y * 128 + row;
                const int ng = blockIdx.x * 256 + col;
                if constexpr (MODE == 0) {
                    const int bb = mg / 768, l = mg - bb * 768;
                    const int hh = ng >> 6, dd = ng & 63;
                    float* dst = OUT + (((size_t)(bb * 16 + hh) * 768) + l) * 64 + dd;
                    dst[0] = to_tf32(c0 + bias[ng]);
                    dst[1] = to_tf32(c1 + bias[ng + 1]);
                } else if constexpr (MODE == 1) {
                    const int bb = mg / 768, l = mg - bb * 768;
                    const int hh = ng >> 6, dd = ng & 63;
                    g_Vt[((size_t)(bb * 16 + hh) * 64 + dd    ) * 768 + l] = to_tf32(c0 + bias[ng]);
                    g_Vt[((size_t)(bb * 16 + hh) * 64 + dd + 1) * 768 + l] = to_tf32(c1 + bias[ng + 1]);
                } else {
                    float* dst = OUT + (size_t)mg * 1024 + ng;
                    dst[0] = c0 + bias[ng];
                    dst[1] = c1 + bias[ng + 1];
                }
            }
        }
    }
}

// ---------------------------------------------------------------------------
// Fused scores + rel + exp + rowsum (R7-proven). One CTA per (qt, bh).
// ---------------------------------------------------------------------------
__global__ __launch_bounds__(256)
void scores_fused()
{
    extern __shared__ float sm[];
    float* Bbuf = sm;                       // [2][128*68]
    float* Wbuf = sm + 2 * 128 * 68;        // [2][128*132]
    const uint32_t bb_a = smem_u32(Bbuf);
    const uint32_t wq_a = smem_u32(Wbuf);   // Q staged here temporarily
    __shared__ float ssum[128];

    const int tid  = threadIdx.x;
    const int lane = tid & 31, wid = tid >> 5;
    const int g4 = lane >> 2, cq = lane & 3;
    const int wm = (wid & 3) * 32, wn = (wid >> 2) * 64;
    const int qt = blockIdx.x, bh = blockIdx.y;

    if (tid < 128) ssum[tid] = 0.f;

    const float* Qg = g_Qp + ((size_t)bh * 768 + qt * 128) * 64;
    const float* Kg = g_Kp + (size_t)bh * 768 * 64;
    const int base0 = 640 - qt * 128;

#pragma unroll
    for (int i = 0; i < 8; ++i) {
        int idx = tid + i * 256;
        int r = idx >> 4, seg = idx & 15;
        CP_A16(wq_a + (uint32_t)(r * 68 + seg * 4) * 4, Qg + r * 64 + seg * 4);
    }
    CP_COMMIT();

    auto loadB = [&](int i) {
        const uint32_t base = bb_a + (uint32_t)(i & 1) * (128 * 68 * 4);
        const bool content = (i >= 2) && ((i & 1) == 0);
        if (content) {
            const int xt = (i - 2) >> 1;
            const float* s0 = Kg + (size_t)xt * 128 * 64;
#pragma unroll
            for (int k = 0; k < 8; ++k) {
                int idx = tid + k * 256;
                int r = idx >> 4, seg = idx & 15;
                CP_A16(base + (uint32_t)(r * 68 + seg * 4) * 4, s0 + r * 64 + seg * 4);
            }
        } else {
            const int w = (i < 2) ? i : ((i + 1) >> 1);
            const int jb = base0 + w * 128;
#pragma unroll
            for (int k = 0; k < 8; ++k) {
                int idx = tid + k * 256;
                int r = idx >> 4, seg = idx & 15;
                int j = jb + r;
                int jc = (j > 1534) ? 1534 : j;
                unsigned sz = (j <= 1534) ? 16u : 0u;
                CP_A16Z(base + (uint32_t)(r * 68 + seg * 4) * 4,
                        g_Ec + (size_t)jc * 64 + seg * 4, sz);
            }
        }
    };

    loadB(0); CP_COMMIT();
    loadB(1); CP_COMMIT();

    CP_WAIT2();
    __syncthreads();

    uint32_t afr[8][2][4];
#pragma unroll
    for (int ks = 0; ks < 8; ++ks)
#pragma unroll
        for (int mt = 0; mt < 2; ++mt) {
            const float* q = Wbuf + (wm + mt * 16 + g4) * 68 + ks * 8 + cq;
            afr[ks][mt][0] = __float_as_uint(q[0]);
            afr[ks][mt][1] = __float_as_uint(q[8 * 68]);
            afr[ks][mt][2] = __float_as_uint(q[4]);
            afr[ks][mt][3] = __float_as_uint(q[8 * 68 + 4]);
        }
    __syncthreads();

    CP_WAIT1();
    __syncthreads();

    float rsum[4] = {0.f, 0.f, 0.f, 0.f};

#pragma unroll 1
    for (int i = 0; i < 13; ++i) {
        const float* Bsb = Bbuf + (i & 1) * (128 * 68);
        float acc[2][8][4] = {};

#pragma unroll
        for (int ks = 0; ks < 8; ++ks) {
            uint32_t bfr[8][2];
#pragma unroll
            for (int nt = 0; nt < 8; ++nt) {
                const float* b = Bsb + (wn + nt * 8 + g4) * 68 + ks * 8 + cq;
                bfr[nt][0] = __float_as_uint(b[0]);
                bfr[nt][1] = __float_as_uint(b[4]);
            }
#pragma unroll
            for (int mt = 0; mt < 2; ++mt)
#pragma unroll
                for (int nt = 0; nt < 8; ++nt)
                    mma_tf32(acc[mt][nt], afr[ks][mt], bfr[nt]);
        }

        const bool content = (i >= 2) && ((i & 1) == 0);
        if (!content) {
            const int w = (i < 2) ? i : ((i + 1) >> 1);
            float* Wd = Wbuf + (w & 1) * (128 * 132);
#pragma unroll
            for (int mt = 0; mt < 2; ++mt)
#pragma unroll
                for (int h2 = 0; h2 < 2; ++h2) {
                    const int row = wm + mt * 16 + g4 + h2 * 8;
#pragma unroll
                    for (int nt = 0; nt < 8; ++nt) {
                        const int col = wn + nt * 8 + 2 * cq;
                        Wd[row * 132 + col    ] = acc[mt][nt][h2 * 2 + 0];
                        Wd[row * 132 + col + 1] = acc[mt][nt][h2 * 2 + 1];
                    }
                }
        } else {
            const int xt = (i - 2) >> 1;
            const float* W0 = Wbuf + (xt & 1) * (128 * 132);
            const float* W1 = Wbuf + ((xt + 1) & 1) * (128 * 132);
            float* Sd = g_S + ((size_t)bh * 768 + qt * 128) * 768 + xt * 128;
#pragma unroll
            for (int mt = 0; mt < 2; ++mt)
#pragma unroll
                for (int h2 = 0; h2 < 2; ++h2) {
                    const int row = wm + mt * 16 + g4 + h2 * 8;
                    float rs = 0.f;
#pragma unroll
                    for (int nt = 0; nt < 8; ++nt) {
                        const int col = wn + nt * 8 + 2 * cq;
                        const int c0 = col - row + 127;
                        const int c1 = c0 + 1;
                        const float r0 = (c0 < 128) ? W0[row * 132 + c0]
                                                    : W1[row * 132 + c0 - 128];
                        const float r1 = (c1 < 128) ? W0[row * 132 + c1]
                                                    : W1[row * 132 + c1 - 128];
                        const float p0 = __expf(SCALE * (acc[mt][nt][h2 * 2 + 0] + r0));
                        const float p1 = __expf(SCALE * (acc[mt][nt][h2 * 2 + 1] + r1));
                        rs += p0 + p1;
                        *(float2*)&Sd[(size_t)row * 768 + col] =
                            make_float2(to_tf32(p0), to_tf32(p1));
                    }
                    rsum[mt * 2 + h2] += rs;
                }
        }

        __syncthreads();
        if (i + 2 < 13) { loadB(i + 2); CP_COMMIT(); }
        if (i + 1 < 13) {
            if (i + 2 < 13) { CP_WAIT1(); } else { CP_WAIT0(); }
            __syncthreads();
        }
    }

#pragma unroll
    for (int k = 0; k < 4; ++k) {
        rsum[k] += __shfl_xor_sync(0xffffffffu, rsum[k], 1);
        rsum[k] += __shfl_xor_sync(0xffffffffu, rsum[k], 2);
    }
    __syncthreads();
    if (cq == 0) {
#pragma unroll
        for (int k = 0; k < 4; ++k) {
            const int row = wm + (k >> 1) * 16 + g4 + (k & 1) * 8;
            atomicAdd(&ssum[row], rsum[k]);
        }
    }
    __syncthreads();
    if (tid < 128)
        g_InvSum[bh * 768 + qt * 128 + tid] = 1.0f / ssum[tid];
}

// ---------------------------------------------------------------------------
// AV GEMM (R6-proven): C[128,64] = P @ Vt^T per (qt,bh); epilogue normalize.
// ---------------------------------------------------------------------------
__global__ __launch_bounds__(256)
void av_mma()
{
    extern __shared__ float sm[];
    constexpr int ASZ = 128 * 68, BSZ = 64 * 68, STG = ASZ + BSZ;
    const uint32_t smb = smem_u32(sm);

    const int tid = threadIdx.x, lane = tid & 31, wid = tid >> 5;
    const int g4 = lane >> 2, cq = lane & 3;
    const int wm = (wid & 3) * 32, wn = (wid >> 2) * 32;
    const int qt = blockIdx.x, bh = blockIdx.y;

    const float* P = g_S  + ((size_t)bh * 768 + qt * 128) * 768;
    const float* V = g_Vt + (size_t)bh * 64 * 768;

    auto load = [&](int t, int s) {
        const uint32_t base = smb + (uint32_t)s * STG * 4;
        const int k0 = t * 64;
#pragma unroll
        for (int i = 0; i < 8; ++i) {
            int idx = tid + i * 256;
            int r = idx >> 4, seg = idx & 15;
            CP_A16(base + (uint32_t)(r * 68 + seg * 4) * 4,
                   P + (size_t)r * 768 + k0 + seg * 4);
        }
#pragma unroll
        for (int i = 0; i < 4; ++i) {
            int idx = tid + i * 256;
            int r = idx >> 4, seg = idx & 15;
            CP_A16(base + (uint32_t)(ASZ + r * 68 + seg * 4) * 4,
                   V + (size_t)r * 768 + k0 + seg * 4);
        }
    };

    float acc[2][4][4] = {};

    load(0, 0); CP_COMMIT();
    load(1, 1); CP_COMMIT();
    CP_WAIT1();
    __syncthreads();

#pragma unroll 1
    for (int t = 0; t < 12; ++t) {
        const float* As = sm + (t & 1) * STG;
        const float* Bs = As + ASZ;
#pragma unroll
        for (int ks = 0; ks < 8; ++ks) {
            uint32_t afr[2][4], bfr[4][2];
#pragma unroll
            for (int mt = 0; mt < 2; ++mt) {
                const float* p = As + (wm + mt * 16 + g4) * 68 + ks * 8 + cq;
                afr[mt][0] = __float_as_uint(p[0]);
                afr[mt][1] = __float_as_uint(p[8 * 68]);
                afr[mt][2] = __float_as_uint(p[4]);
                afr[mt][3] = __float_as_uint(p[8 * 68 + 4]);
            }
#pragma unroll
            for (int nt = 0; nt < 4; ++nt) {
                const float* p = Bs + (wn + nt * 8 + g4) * 68 + ks * 8 + cq;
                bfr[nt][0] = __float_as_uint(p[0]);
                bfr[nt][1] = __float_as_uint(p[4]);
            }
#pragma unroll
            for (int mt = 0; mt < 2; ++mt)
#pragma unroll
                for (int nt = 0; nt < 4; ++nt)
                    mma_tf32(acc[mt][nt], afr[mt], bfr[nt]);
        }
        __syncthreads();
        if (t + 2 < 12) { load(t + 2, t & 1); CP_COMMIT(); }
        if (t + 1 < 12) {
            if (t + 2 < 12) { CP_WAIT1(); } else { CP_WAIT0(); }
            __syncthreads();
        }
    }

    const int b = bh >> 4, h = bh & 15;
#pragma unroll
    for (int mt = 0; mt < 2; ++mt)
#pragma unroll
        for (int h2 = 0; h2 < 2; ++h2) {
            const int row = wm + mt * 16 + g4 + h2 * 8;
            const float inv = g_InvSum[bh * 768 + qt * 128 + row];
#pragma unroll
            for (int nt = 0; nt < 4; ++nt) {
                const int col = wn + nt * 8 + 2 * cq;
                *(float2*)&g_O2[((size_t)(b * 768) + qt * 128 + row) * 1024
                                + h * 64 + col] =
                    make_float2(to_tf32(acc[mt][nt][h2 * 2 + 0] * inv),
                                to_tf32(acc[mt][nt][h2 * 2 + 1] * inv));
            }
        }
}

// ---------------------------------------------------------------------------
extern "C" void kernel_launch(void* const* d_in, const int* in_sizes, int n_in,
                              void* d_out, int out_size)
{
    const float* query = (const float*)d_in[0];
    const float* key   = (const float*)d_in[1];
    const float* value = (const float*)d_in[2];
    const float* w_q   = (const float*)d_in[3];
    const float* b_q   = (const float*)d_in[4];
    const float* w_k   = (const float*)d_in[5];
    const float* b_k   = (const float*)d_in[6];
    const float* w_v   = (const float*)d_in[7];
    const float* b_v   = (const float*)d_in[8];
    const float* w_o   = (const float*)d_in[9];
    const float* b_o   = (const float*)d_in[10];
    const float* relE  = (const float*)d_in[11];
    float* out = (float*)d_out;

    float *xr, *wq, *wk, *wv, *wo, *qp, *kp, *o2, *ec;
    cudaGetSymbolAddress((void**)&xr, g_Xr);
    cudaGetSymbolAddress((void**)&wq, g_Wq);
    cudaGetSymbolAddress((void**)&wk, g_Wk);
    cudaGetSymbolAddress((void**)&wv, g_Wv);
    cudaGetSymbolAddress((void**)&wo, g_Wo);
    cudaGetSymbolAddress((void**)&qp, g_Qp);
    cudaGetSymbolAddress((void**)&kp, g_Kp);
    cudaGetSymbolAddress((void**)&o2, g_O2);
    cudaGetSymbolAddress((void**)&ec, g_Ec);

    const int SMEMP   = 3 * (128 + 256) * 20 * 4;                // 92160
    const int SC_SMEM = (2 * 128 * 68 + 2 * 128 * 132) * 4;      // 204800
    const int AV_SMEM = 2 * (128 * 68 + 64 * 68) * 4;            // 104448
    cudaFuncSetAttribute(proj_mma<0>, cudaFuncAttributeMaxDynamicSharedMemorySize, SMEMP);
    cudaFuncSetAttribute(proj_mma<1>, cudaFuncAttributeMaxDynamicSharedMemorySize, SMEMP);
    cudaFuncSetAttribute(proj_mma<2>, cudaFuncAttributeMaxDynamicSharedMemorySize, SMEMP);
    cudaFuncSetAttribute(scores_fused, cudaFuncAttributeMaxDynamicSharedMemorySize, SC_SMEM);
    cudaFuncSetAttribute(av_mma,       cudaFuncAttributeMaxDynamicSharedMemorySize, AV_SMEM);

    const int NW4 = 1024 * 1024 / 4;
    const int NX4 = M_ * D_ / 4;
    conv_tf32<<<(NW4 + 255) / 256, 256>>>((const float4*)w_q, (float4*)wq, NW4);
    conv_tf32<<<(NW4 + 255) / 256, 256>>>((const float4*)w_k, (float4*)wk, NW4);
    conv_tf32<<<(NW4 + 255) / 256, 256>>>((const float4*)w_v, (float4*)wv, NW4);
    conv_tf32<<<(NW4 + 255) / 256, 256>>>((const float4*)w_o, (float4*)wo, NW4);
    conv_tf32<<<(1535 * 64 / 4 + 255) / 256, 256>>>((const float4*)relE, (float4*)ec, 1535 * 64 / 4);

    conv_tf32<<<(NX4 + 255) / 256, 256>>>((const float4*)query, (float4*)xr, NX4);
    proj_mma<0><<<dim3(4, 48), 256, SMEMP>>>(xr, wq, b_q, qp);
    conv_tf32<<<(NX4 + 255) / 256, 256>>>((const float4*)key, (float4*)xr, NX4);
    proj_mma<0><<<dim3(4, 48), 256, SMEMP>>>(xr, wk, b_k, kp);
    conv_tf32<<<(NX4 + 255) / 256, 256>>>((const float4*)value, (float4*)xr, NX4);
    proj_mma<1><<<dim3(4, 48), 256, SMEMP>>>(xr, wv, b_v, nullptr);

    scores_fused<<<dim3(6, 128), 256, SC_SMEM>>>();
    av_mma<<<dim3(6, 128), 256, AV_SMEM>>>();

    proj_mma<2><<<dim3(4, 48), 256, SMEMP>>>(o2, wo, b_o, out);
}

// round 9
// speedup vs baseline: 1.2212x; 1.2212x over previous
#include <cuda_runtime.h>
#include <cstdint>

#define B_    8
#define L_    768
#define H_    16
#define DK_   64
#define D_    1024
#define BH_   128
#define M_    6144
#define SCALE 0.125f

// Scratch (device globals; allocation forbidden)
__device__ float g_Xr[3][M_ * D_];                     // tf32 inputs: q, k, v
__device__ float g_Wq[D_ * D_], g_Wk[D_ * D_], g_Wv[D_ * D_], g_Wo[D_ * D_];
__device__ float g_Qp[BH_ * L_ * DK_];                 // [bh][l][dk] tf32
__device__ float g_Kp[BH_ * L_ * DK_];                 // tf32
__device__ float g_Vt[BH_ * DK_ * L_];                 // V^T [bh][dk][l] tf32
__device__ float g_Ec[1535 * 64];                      // tf32 rel embedding
__device__ float g_S [(size_t)BH_ * L_ * L_];          // unnormalized probs (tf32)
__device__ float g_InvSum[BH_ * L_];                   // 1/rowsum
__device__ float g_O2[(size_t)M_ * D_];                // attn out, merged, tf32

__device__ __forceinline__ float to_tf32(float x) {
    float r;
    asm("cvt.rna.tf32.f32 %0, %1;" : "=f"(r) : "f"(x));
    return r;
}
__device__ __forceinline__ uint32_t smem_u32(const void* p) {
    uint32_t a;
    asm("{ .reg .u64 t; cvta.to.shared.u64 t, %1; cvt.u32.u64 %0, t; }"
        : "=r"(a) : "l"(p));
    return a;
}
__device__ __forceinline__ void mma_tf32(float* d, const uint32_t* a, const uint32_t* b) {
    asm volatile(
        "mma.sync.aligned.m16n8k8.row.col.f32.tf32.tf32.f32 "
        "{%0,%1,%2,%3}, {%4,%5,%6,%7}, {%8,%9}, {%0,%1,%2,%3};"
        : "+f"(d[0]), "+f"(d[1]), "+f"(d[2]), "+f"(d[3])
        : "r"(a[0]), "r"(a[1]), "r"(a[2]), "r"(a[3]), "r"(b[0]), "r"(b[1]));
}
#define CP_A16(dst, src) \
    asm volatile("cp.async.ca.shared.global [%0], [%1], 16;" :: "r"(dst), "l"(src) : "memory")
#define CP_A16Z(dst, src, sz) \
    asm volatile("cp.async.ca.shared.global [%0], [%1], 16, %2;" :: "r"(dst), "l"(src), "r"(sz) : "memory")
#define CP_COMMIT() asm volatile("cp.async.commit_group;" ::: "memory")
#define CP_WAIT2()  asm volatile("cp.async.wait_group 2;" ::: "memory")
#define CP_WAIT1()  asm volatile("cp.async.wait_group 1;" ::: "memory")
#define CP_WAIT0()  asm volatile("cp.async.wait_group 0;" ::: "memory")

// ---------------------------------------------------------------------------
// tf32 pre-round, z-batched over up to 4 arrays
// ---------------------------------------------------------------------------
__global__ __launch_bounds__(256)
void conv_tf32_z(const float4* __restrict__ p0, const float4* __restrict__ p1,
                 const float4* __restrict__ p2, const float4* __restrict__ p3,
                 float4* __restrict__ d0, float4* __restrict__ d1,
                 float4* __restrict__ d2, float4* __restrict__ d3, int n4)
{
    const int z = blockIdx.z;
    const float4* in  = (z == 0) ? p0 : (z == 1) ? p1 : (z == 2) ? p2 : p3;
    float4*       out = (z == 0) ? d0 : (z == 1) ? d1 : (z == 2) ? d2 : d3;
    int i = blockIdx.x * 256 + threadIdx.x;
    if (i < n4) {
        float4 v = in[i];
        out[i] = make_float4(to_tf32(v.x), to_tf32(v.y), to_tf32(v.z), to_tf32(v.w));
    }
}
__global__ __launch_bounds__(256)
void conv_tf32(const float4* __restrict__ in, float4* __restrict__ out, int n4)
{
    int i = blockIdx.x * 256 + threadIdx.x;
    if (i < n4) {
        float4 v = in[i];
        out[i] = make_float4(to_tf32(v.x), to_tf32(v.y), to_tf32(v.z), to_tf32(v.w));
    }
}

// ---------------------------------------------------------------------------
// QKV projection, fused over blockIdx.z (0=Q, 1=K, 2=V). R7-proven body:
// C[128,128] tile, BK=32, 3-stage cp.async, stride-36 smem, warps 2m x 4n.
// ---------------------------------------------------------------------------
__global__ __launch_bounds__(256)
void proj_qkv(const float* __restrict__ bq, const float* __restrict__ bk,
              const float* __restrict__ bv, float* __restrict__ Qout,
              float* __restrict__ Kout)
{
    extern __shared__ float sm[];
    const uint32_t smb = smem_u32(sm);
    constexpr int STG = 2 * 128 * 36;

    const int tid = threadIdx.x, lane = tid & 31, wid = tid >> 5;
    const int g4 = lane >> 2, cq = lane & 3;
    const int wm = (wid & 1) * 64, wn = (wid >> 1) * 32;
    const int z = blockIdx.z;

    const float* Ag = g_Xr[z];
    const float* Bg = (z == 0) ? g_Wq : (z == 1) ? g_Wk : g_Wv;
    const float* bias = (z == 0) ? bq : (z == 1) ? bk : bv;

    const float* Arow = Ag + (size_t)(blockIdx.y * 128) * 1024;
    const float* Brow = Bg + (size_t)(blockIdx.x * 128) * 1024;

    auto loadAB = [&](int t, int s) {
        const uint32_t base = smb + (uint32_t)s * STG * 4;
        const int k0 = t * 32;
#pragma unroll
        for (int i = 0; i < 4; ++i) {
            int idx = tid + i * 256;
            int r = idx >> 3, seg = idx & 7;
            CP_A16(base + (uint32_t)(r * 36 + seg * 4) * 4,
                   Arow + (size_t)r * 1024 + k0 + seg * 4);
        }
#pragma unroll
        for (int i = 0; i < 4; ++i) {
            int idx = tid + i * 256;
            int r = idx >> 3, seg = idx & 7;
            CP_A16(base + (uint32_t)(128 * 36 + r * 36 + seg * 4) * 4,
                   Brow + (size_t)r * 1024 + k0 + seg * 4);
        }
    };

    float acc[4][4][4] = {};

    loadAB(0, 0); CP_COMMIT();
    loadAB(1, 1); CP_COMMIT();

    for (int t = 0; t < 32; ++t) {
        if (t < 31) { CP_WAIT1(); } else { CP_WAIT0(); }
        __syncthreads();
        if (t + 2 < 32) { loadAB(t + 2, (t + 2) % 3); CP_COMMIT(); }

        const float* As = sm + (t % 3) * STG;
        const float* Bs = As + 128 * 36;
#pragma unroll
        for (int ks = 0; ks < 4; ++ks) {
            uint32_t afr[4][4], bfr[4][2];
#pragma unroll
            for (int m = 0; m < 4; ++m) {
                const float* p = As + (wm + m * 16 + g4) * 36 + ks * 8 + cq;
                afr[m][0] = __float_as_uint(p[0]);
                afr[m][1] = __float_as_uint(p[8 * 36]);
                afr[m][2] = __float_as_uint(p[4]);
                afr[m][3] = __float_as_uint(p[8 * 36 + 4]);
            }
#pragma unroll
            for (int n = 0; n < 4; ++n) {
                const float* p = Bs + (wn + n * 8 + g4) * 36 + ks * 8 + cq;
                bfr[n][0] = __float_as_uint(p[0]);
                bfr[n][1] = __float_as_uint(p[4]);
            }
#pragma unroll
            for (int m = 0; m < 4; ++m)
#pragma unroll
                for (int n = 0; n < 4; ++n)
                    mma_tf32(acc[m][n], afr[m], bfr[n]);
        }
    }

    float* OUT = (z == 0) ? Qout : Kout;
#pragma unroll
    for (int m = 0; m < 4; ++m) {
#pragma unroll
        for (int n = 0; n < 4; ++n) {
            const int col = wn + n * 8 + cq * 2;
#pragma unroll
            for (int h2 = 0; h2 < 2; ++h2) {
                const int row = wm + m * 16 + g4 + h2 * 8;
                const float c0 = acc[m][n][h2 * 2 + 0];
                const float c1 = acc[m][n][h2 * 2 + 1];
                const int mg = blockIdx.y * 128 + row;
                const int ng = blockIdx.x * 128 + col;
                const int bb = mg / 768, l = mg - bb * 768;
                const int hh = ng >> 6, dd = ng & 63;
                if (z < 2) {
                    float* dst = OUT + (((size_t)(bb * 16 + hh) * 768) + l) * 64 + dd;
                    dst[0] = to_tf32(c0 + bias[ng]);
                    dst[1] = to_tf32(c1 + bias[ng + 1]);
                } else {
                    g_Vt[((size_t)(bb * 16 + hh) * 64 + dd    ) * 768 + l] = to_tf32(c0 + bias[ng]);
                    g_Vt[((size_t)(bb * 16 + hh) * 64 + dd + 1) * 768 + l] = to_tf32(c1 + bias[ng + 1]);
                }
            }
        }
    }
}

// ---------------------------------------------------------------------------
// Output projection (R7-proven): C = O2 @ Wo^T + bias, plain fp32 OUT.
// ---------------------------------------------------------------------------
__global__ __launch_bounds__(256)
void proj_out(const float* __restrict__ bias, float* __restrict__ OUT)
{
    extern __shared__ float sm[];
    const uint32_t smb = smem_u32(sm);
    constexpr int STG = 2 * 128 * 36;

    const int tid = threadIdx.x, lane = tid & 31, wid = tid >> 5;
    const int g4 = lane >> 2, cq = lane & 3;
    const int wm = (wid & 1) * 64, wn = (wid >> 1) * 32;

    const float* Arow = g_O2 + (size_t)(blockIdx.y * 128) * 1024;
    const float* Brow = g_Wo + (size_t)(blockIdx.x * 128) * 1024;

    auto loadAB = [&](int t, int s) {
        const uint32_t base = smb + (uint32_t)s * STG * 4;
        const int k0 = t * 32;
#pragma unroll
        for (int i = 0; i < 4; ++i) {
            int idx = tid + i * 256;
            int r = idx >> 3, seg = idx & 7;
            CP_A16(base + (uint32_t)(r * 36 + seg * 4) * 4,
                   Arow + (size_t)r * 1024 + k0 + seg * 4);
        }
#pragma unroll
        for (int i = 0; i < 4; ++i) {
            int idx = tid + i * 256;
            int r = idx >> 3, seg = idx & 7;
            CP_A16(base + (uint32_t)(128 * 36 + r * 36 + seg * 4) * 4,
                   Brow + (size_t)r * 1024 + k0 + seg * 4);
        }
    };

    float acc[4][4][4] = {};

    loadAB(0, 0); CP_COMMIT();
    loadAB(1, 1); CP_COMMIT();

    for (int t = 0; t < 32; ++t) {
        if (t < 31) { CP_WAIT1(); } else { CP_WAIT0(); }
        __syncthreads();
        if (t + 2 < 32) { loadAB(t + 2, (t + 2) % 3); CP_COMMIT(); }

        const float* As = sm + (t % 3) * STG;
        const float* Bs = As + 128 * 36;
#pragma unroll
        for (int ks = 0; ks < 4; ++ks) {
            uint32_t afr[4][4], bfr[4][2];
#pragma unroll
            for (int m = 0; m < 4; ++m) {
                const float* p = As + (wm + m * 16 + g4) * 36 + ks * 8 + cq;
                afr[m][0] = __float_as_uint(p[0]);
                afr[m][1] = __float_as_uint(p[8 * 36]);
                afr[m][2] = __float_as_uint(p[4]);
                afr[m][3] = __float_as_uint(p[8 * 36 + 4]);
            }
#pragma unroll
            for (int n = 0; n < 4; ++n) {
                const float* p = Bs + (wn + n * 8 + g4) * 36 + ks * 8 + cq;
                bfr[n][0] = __float_as_uint(p[0]);
                bfr[n][1] = __float_as_uint(p[4]);
            }
#pragma unroll
            for (int m = 0; m < 4; ++m)
#pragma unroll
                for (int n = 0; n < 4; ++n)
                    mma_tf32(acc[m][n], afr[m], bfr[n]);
        }
    }

#pragma unroll
    for (int m = 0; m < 4; ++m) {
#pragma unroll
        for (int n = 0; n < 4; ++n) {
            const int col = wn + n * 8 + cq * 2;
#pragma unroll
            for (int h2 = 0; h2 < 2; ++h2) {
                const int row = wm + m * 16 + g4 + h2 * 8;
                const int mg = blockIdx.y * 128 + row;
                const int ng = blockIdx.x * 128 + col;
                float* dst = OUT + (size_t)mg * 1024 + ng;
                dst[0] = acc[m][n][h2 * 2 + 0] + bias[ng];
                dst[1] = acc[m][n][h2 * 2 + 1] + bias[ng + 1];
            }
        }
    }
}

// ---------------------------------------------------------------------------
// Fused scores + rel + exp + rowsum (R7-proven). One CTA per (qt, bh).
// ---------------------------------------------------------------------------
__global__ __launch_bounds__(256)
void scores_fused()
{
    extern __shared__ float sm[];
    float* Bbuf = sm;                       // [2][128*68]
    float* Wbuf = sm + 2 * 128 * 68;        // [2][128*132]
    const uint32_t bb_a = smem_u32(Bbuf);
    const uint32_t wq_a = smem_u32(Wbuf);
    __shared__ float ssum[128];

    const int tid  = threadIdx.x;
    const int lane = tid & 31, wid = tid >> 5;
    const int g4 = lane >> 2, cq = lane & 3;
    const int wm = (wid & 3) * 32, wn = (wid >> 2) * 64;
    const int qt = blockIdx.x, bh = blockIdx.y;

    if (tid < 128) ssum[tid] = 0.f;

    const float* Qg = g_Qp + ((size_t)bh * 768 + qt * 128) * 64;
    const float* Kg = g_Kp + (size_t)bh * 768 * 64;
    const int base0 = 640 - qt * 128;

#pragma unroll
    for (int i = 0; i < 8; ++i) {
        int idx = tid + i * 256;
        int r = idx >> 4, seg = idx & 15;
        CP_A16(wq_a + (uint32_t)(r * 68 + seg * 4) * 4, Qg + r * 64 + seg * 4);
    }
    CP_COMMIT();

    auto loadB = [&](int i) {
        const uint32_t base = bb_a + (uint32_t)(i & 1) * (128 * 68 * 4);
        const bool content = (i >= 2) && ((i & 1) == 0);
        if (content) {
            const int xt = (i - 2) >> 1;
            const float* s0 = Kg + (size_t)xt * 128 * 64;
#pragma unroll
            for (int k = 0; k < 8; ++k) {
                int idx = tid + k * 256;
                int r = idx >> 4, seg = idx & 15;
                CP_A16(base + (uint32_t)(r * 68 + seg * 4) * 4, s0 + r * 64 + seg * 4);
            }
        } else {
            const int w = (i < 2) ? i : ((i + 1) >> 1);
            const int jb = base0 + w * 128;
#pragma unroll
            for (int k = 0; k < 8; ++k) {
                int idx = tid + k * 256;
                int r = idx >> 4, seg = idx & 15;
                int j = jb + r;
                int jc = (j > 1534) ? 1534 : j;
                unsigned sz = (j <= 1534) ? 16u : 0u;
                CP_A16Z(base + (uint32_t)(r * 68 + seg * 4) * 4,
                        g_Ec + (size_t)jc * 64 + seg * 4, sz);
            }
        }
    };

    loadB(0); CP_COMMIT();
    loadB(1); CP_COMMIT();

    CP_WAIT2();
    __syncthreads();

    uint32_t afr[8][2][4];
#pragma unroll
    for (int ks = 0; ks < 8; ++ks)
#pragma unroll
        for (int mt = 0; mt < 2; ++mt) {
            const float* q = Wbuf + (wm + mt * 16 + g4) * 68 + ks * 8 + cq;
            afr[ks][mt][0] = __float_as_uint(q[0]);
            afr[ks][mt][1] = __float_as_uint(q[8 * 68]);
            afr[ks][mt][2] = __float_as_uint(q[4]);
            afr[ks][mt][3] = __float_as_uint(q[8 * 68 + 4]);
        }
    __syncthreads();

    CP_WAIT1();
    __syncthreads();

    float rsum[4] = {0.f, 0.f, 0.f, 0.f};

#pragma unroll 1
    for (int i = 0; i < 13; ++i) {
        const float* Bsb = Bbuf + (i & 1) * (128 * 68);
        float acc[2][8][4] = {};

#pragma unroll
        for (int ks = 0; ks < 8; ++ks) {
            uint32_t bfr[8][2];
#pragma unroll
            for (int nt = 0; nt < 8; ++nt) {
                const float* b = Bsb + (wn + nt * 8 + g4) * 68 + ks * 8 + cq;
                bfr[nt][0] = __float_as_uint(b[0]);
                bfr[nt][1] = __float_as_uint(b[4]);
            }
#pragma unroll
            for (int mt = 0; mt < 2; ++mt)
#pragma unroll
                for (int nt = 0; nt < 8; ++nt)
                    mma_tf32(acc[mt][nt], afr[ks][mt], bfr[nt]);
        }

        const bool content = (i >= 2) && ((i & 1) == 0);
        if (!content) {
            const int w = (i < 2) ? i : ((i + 1) >> 1);
            float* Wd = Wbuf + (w & 1) * (128 * 132);
#pragma unroll
            for (int mt = 0; mt < 2; ++mt)
#pragma unroll
                for (int h2 = 0; h2 < 2; ++h2) {
                    const int row = wm + mt * 16 + g4 + h2 * 8;
#pragma unroll
                    for (int nt = 0; nt < 8; ++nt) {
                        const int col = wn + nt * 8 + 2 * cq;
                        Wd[row * 132 + col    ] = acc[mt][nt][h2 * 2 + 0];
                        Wd[row * 132 + col + 1] = acc[mt][nt][h2 * 2 + 1];
                    }
                }
        } else {
            const int xt = (i - 2) >> 1;
            const float* W0 = Wbuf + (xt & 1) * (128 * 132);
            const float* W1 = Wbuf + ((xt + 1) & 1) * (128 * 132);
            float* Sd = g_S + ((size_t)bh * 768 + qt * 128) * 768 + xt * 128;
#pragma unroll
            for (int mt = 0; mt < 2; ++mt)
#pragma unroll
                for (int h2 = 0; h2 < 2; ++h2) {
                    const int row = wm + mt * 16 + g4 + h2 * 8;
                    float rs = 0.f;
#pragma unroll
                    for (int nt = 0; nt < 8; ++nt) {
                        const int col = wn + nt * 8 + 2 * cq;
                        const int c0 = col - row + 127;
                        const int c1 = c0 + 1;
                        const float r0 = (c0 < 128) ? W0[row * 132 + c0]
                                                    : W1[row * 132 + c0 - 128];
                        const float r1 = (c1 < 128) ? W0[row * 132 + c1]
                                                    : W1[row * 132 + c1 - 128];
                        const float p0 = __expf(SCALE * (acc[mt][nt][h2 * 2 + 0] + r0));
                        const float p1 = __expf(SCALE * (acc[mt][nt][h2 * 2 + 1] + r1));
                        rs += p0 + p1;
                        *(float2*)&Sd[(size_t)row * 768 + col] =
                            make_float2(to_tf32(p0), to_tf32(p1));
                    }
                    rsum[mt * 2 + h2] += rs;
                }
        }

        __syncthreads();
        if (i + 2 < 13) { loadB(i + 2); CP_COMMIT(); }
        if (i + 1 < 13) {
            if (i + 2 < 13) { CP_WAIT1(); } else { CP_WAIT0(); }
            __syncthreads();
        }
    }

#pragma unroll
    for (int k = 0; k < 4; ++k) {
        rsum[k] += __shfl_xor_sync(0xffffffffu, rsum[k], 1);
        rsum[k] += __shfl_xor_sync(0xffffffffu, rsum[k], 2);
    }
    __syncthreads();
    if (cq == 0) {
#pragma unroll
        for (int k = 0; k < 4; ++k) {
            const int row = wm + (k >> 1) * 16 + g4 + (k & 1) * 8;
            atomicAdd(&ssum[row], rsum[k]);
        }
    }
    __syncthreads();
    if (tid < 128)
        g_InvSum[bh * 768 + qt * 128 + tid] = 1.0f / ssum[tid];
}

// ---------------------------------------------------------------------------
// AV GEMM (R6-proven): C[128,64] = P @ Vt^T per (qt,bh); epilogue normalize.
// ---------------------------------------------------------------------------
__global__ __launch_bounds__(256)
void av_mma()
{
    extern __shared__ float sm[];
    constexpr int ASZ = 128 * 68, BSZ = 64 * 68, STG = ASZ + BSZ;
    const uint32_t smb = smem_u32(sm);

    const int tid = threadIdx.x, lane = tid & 31, wid = tid >> 5;
    const int g4 = lane >> 2, cq = lane & 3;
    const int wm = (wid & 3) * 32, wn = (wid >> 2) * 32;
    const int qt = blockIdx.x, bh = blockIdx.y;

    const float* P = g_S  + ((size_t)bh * 768 + qt * 128) * 768;
    const float* V = g_Vt + (size_t)bh * 64 * 768;

    auto load = [&](int t, int s) {
        const uint32_t base = smb + (uint32_t)s * STG * 4;
        const int k0 = t * 64;
#pragma unroll
        for (int i = 0; i < 8; ++i) {
            int idx = tid + i * 256;
            int r = idx >> 4, seg = idx & 15;
            CP_A16(base + (uint32_t)(r * 68 + seg * 4) * 4,
                   P + (size_t)r * 768 + k0 + seg * 4);
        }
#pragma unroll
        for (int i = 0; i < 4; ++i) {
            int idx = tid + i * 256;
            int r = idx >> 4, seg = idx & 15;
            CP_A16(base + (uint32_t)(ASZ + r * 68 + seg * 4) * 4,
                   V + (size_t)r * 768 + k0 + seg * 4);
        }
    };

    float acc[2][4][4] = {};

    load(0, 0); CP_COMMIT();
    load(1, 1); CP_COMMIT();
    CP_WAIT1();
    __syncthreads();

#pragma unroll 1
    for (int t = 0; t < 12; ++t) {
        const float* As = sm + (t & 1) * STG;
        const float* Bs = As + ASZ;
#pragma unroll
        for (int ks = 0; ks < 8; ++ks) {
            uint32_t afr[2][4], bfr[4][2];
#pragma unroll
            for (int mt = 0; mt < 2; ++mt) {
                const float* p = As + (wm + mt * 16 + g4) * 68 + ks * 8 + cq;
                afr[mt][0] = __float_as_uint(p[0]);
                afr[mt][1] = __float_as_uint(p[8 * 68]);
                afr[mt][2] = __float_as_uint(p[4]);
                afr[mt][3] = __float_as_uint(p[8 * 68 + 4]);
            }
#pragma unroll
            for (int nt = 0; nt < 4; ++nt) {
                const float* p = Bs + (wn + nt * 8 + g4) * 68 + ks * 8 + cq;
                bfr[nt][0] = __float_as_uint(p[0]);
                bfr[nt][1] = __float_as_uint(p[4]);
            }
#pragma unroll
            for (int mt = 0; mt < 2; ++mt)
#pragma unroll
                for (int nt = 0; nt < 4; ++nt)
                    mma_tf32(acc[mt][nt], afr[mt], bfr[nt]);
        }
        __syncthreads();
        if (t + 2 < 12) { load(t + 2, t & 1); CP_COMMIT(); }
        if (t + 1 < 12) {
            if (t + 2 < 12) { CP_WAIT1(); } else { CP_WAIT0(); }
            __syncthreads();
        }
    }

    const int b = bh >> 4, h = bh & 15;
#pragma unroll
    for (int mt = 0; mt < 2; ++mt)
#pragma unroll
        for (int h2 = 0; h2 < 2; ++h2) {
            const int row = wm + mt * 16 + g4 + h2 * 8;
            const float inv = g_InvSum[bh * 768 + qt * 128 + row];
#pragma unroll
            for (int nt = 0; nt < 4; ++nt) {
                const int col = wn + nt * 8 + 2 * cq;
                *(float2*)&g_O2[((size_t)(b * 768) + qt * 128 + row) * 1024
                                + h * 64 + col] =
                    make_float2(to_tf32(acc[mt][nt][h2 * 2 + 0] * inv),
                                to_tf32(acc[mt][nt][h2 * 2 + 1] * inv));
            }
        }
}

// ---------------------------------------------------------------------------
extern "C" void kernel_launch(void* const* d_in, const int* in_sizes, int n_in,
                              void* d_out, int out_size)
{
    const float* query = (const float*)d_in[0];
    const float* key   = (const float*)d_in[1];
    const float* value = (const float*)d_in[2];
    const float* w_q   = (const float*)d_in[3];
    const float* b_q   = (const float*)d_in[4];
    const float* w_k   = (const float*)d_in[5];
    const float* b_k   = (const float*)d_in[6];
    const float* w_v   = (const float*)d_in[7];
    const float* b_v   = (const float*)d_in[8];
    const float* w_o   = (const float*)d_in[9];
    const float* b_o   = (const float*)d_in[10];
    const float* relE  = (const float*)d_in[11];
    float* out = (float*)d_out;

    float *xr, *wq, *wk, *wv, *wo, *qp, *kp, *ec;
    cudaGetSymbolAddress((void**)&xr, g_Xr);
    cudaGetSymbolAddress((void**)&wq, g_Wq);
    cudaGetSymbolAddress((void**)&wk, g_Wk);
    cudaGetSymbolAddress((void**)&wv, g_Wv);
    cudaGetSymbolAddress((void**)&wo, g_Wo);
    cudaGetSymbolAddress((void**)&qp, g_Qp);
    cudaGetSymbolAddress((void**)&kp, g_Kp);
    cudaGetSymbolAddress((void**)&ec, g_Ec);

    const int SMEMP   = 3 * 2 * 128 * 36 * 4;                    // 110592
    const int SC_SMEM = (2 * 128 * 68 + 2 * 128 * 132) * 4;      // 204800
    const int AV_SMEM = 2 * (128 * 68 + 64 * 68) * 4;            // 104448
    cudaFuncSetAttribute(proj_qkv, cudaFuncAttributeMaxDynamicSharedMemorySize, SMEMP);
    cudaFuncSetAttribute(proj_out, cudaFuncAttributeMaxDynamicSharedMemorySize, SMEMP);
    cudaFuncSetAttribute(scores_fused, cudaFuncAttributeMaxDynamicSharedMemorySize, SC_SMEM);
    cudaFuncSetAttribute(av_mma,       cudaFuncAttributeMaxDynamicSharedMemorySize, AV_SMEM);

    const int NW4 = 1024 * 1024 / 4;
    const int NX4 = M_ * D_ / 4;

    // weights (4-way z-batched) + rel embedding
    conv_tf32_z<<<dim3((NW4 + 255) / 256, 1, 4), 256>>>(
        (const float4*)w_q, (const float4*)w_k, (const float4*)w_v, (const float4*)w_o,
        (float4*)wq, (float4*)wk, (float4*)wv, (float4*)wo, NW4);
    conv_tf32<<<(1535 * 64 / 4 + 255) / 256, 256>>>(
        (const float4*)relE, (float4*)ec, 1535 * 64 / 4);

    // inputs (3-way z-batched into g_Xr[0..2])
    conv_tf32_z<<<dim3((NX4 + 255) / 256, 1, 3), 256>>>(
        (const float4*)query, (const float4*)key, (const float4*)value,
        (const float4*)query,
        (float4*)(xr), (float4*)(xr + M_ * D_), (float4*)(xr + 2 * M_ * D_),
        (float4*)(xr), NX4);

    // fused QKV projection: one launch, 3 full projections
    proj_qkv<<<dim3(8, 48, 3), 256, SMEMP>>>(b_q, b_k, b_v, qp, kp);

    scores_fused<<<dim3(6, 128), 256, SC_SMEM>>>();
    av_mma<<<dim3(6, 128), 256, AV_SMEM>>>();

    proj_out<<<dim3(8, 48), 256, SMEMP>>>(b_o, out);
}

// round 10
// speedup vs baseline: 1.3089x; 1.0718x over previous
#include <cuda_runtime.h>
#include <cstdint>

#define B_    8
#define L_    768
#define H_    16
#define DK_   64
#define D_    1024
#define BH_   128
#define M_    6144
#define SCALE 0.125f

// Scratch (device globals; allocation forbidden)
__device__ float g_Xr[3][M_ * D_];                     // tf32 inputs: q, k, v
__device__ float g_Wq[D_ * D_], g_Wk[D_ * D_], g_Wv[D_ * D_], g_Wo[D_ * D_];
__device__ float g_Qp[BH_ * L_ * DK_];                 // [bh][l][dk] tf32
__device__ float g_Kp[BH_ * L_ * DK_];                 // tf32
__device__ float g_Vt[BH_ * DK_ * L_];                 // V^T [bh][dk][l] tf32
__device__ float g_Ec[1535 * 64];                      // tf32 rel embedding
__device__ float g_S [(size_t)BH_ * L_ * L_];          // unnormalized probs (tf32)
__device__ float g_InvSum[BH_ * L_];                   // 1/rowsum
__device__ float g_O2[(size_t)M_ * D_];                // attn out, merged, tf32

__device__ __forceinline__ float to_tf32(float x) {
    float r;
    asm("cvt.rna.tf32.f32 %0, %1;" : "=f"(r) : "f"(x));
    return r;
}
__device__ __forceinline__ uint32_t smem_u32(const void* p) {
    uint32_t a;
    asm("{ .reg .u64 t; cvta.to.shared.u64 t, %1; cvt.u32.u64 %0, t; }"
        : "=r"(a) : "l"(p));
    return a;
}
__device__ __forceinline__ void mma_tf32(float* d, const uint32_t* a, const uint32_t* b) {
    asm volatile(
        "mma.sync.aligned.m16n8k8.row.col.f32.tf32.tf32.f32 "
        "{%0,%1,%2,%3}, {%4,%5,%6,%7}, {%8,%9}, {%0,%1,%2,%3};"
        : "+f"(d[0]), "+f"(d[1]), "+f"(d[2]), "+f"(d[3])
        : "r"(a[0]), "r"(a[1]), "r"(a[2]), "r"(a[3]), "r"(b[0]), "r"(b[1]));
}
#define CP_A16(dst, src) \
    asm volatile("cp.async.ca.shared.global [%0], [%1], 16;" :: "r"(dst), "l"(src) : "memory")
#define CP_A16Z(dst, src, sz) \
    asm volatile("cp.async.ca.shared.global [%0], [%1], 16, %2;" :: "r"(dst), "l"(src), "r"(sz) : "memory")
#define CP_COMMIT() asm volatile("cp.async.commit_group;" ::: "memory")
#define CP_WAIT2()  asm volatile("cp.async.wait_group 2;" ::: "memory")
#define CP_WAIT1()  asm volatile("cp.async.wait_group 1;" ::: "memory")
#define CP_WAIT0()  asm volatile("cp.async.wait_group 0;" ::: "memory")

// ---------------------------------------------------------------------------
// tf32 pre-round, z-batched over up to 4 arrays
// ---------------------------------------------------------------------------
__global__ __launch_bounds__(256)
void conv_tf32_z(const float4* __restrict__ p0, const float4* __restrict__ p1,
                 const float4* __restrict__ p2, const float4* __restrict__ p3,
                 float4* __restrict__ d0, float4* __restrict__ d1,
                 float4* __restrict__ d2, float4* __restrict__ d3, int n4)
{
    const int z = blockIdx.z;
    const float4* in  = (z == 0) ? p0 : (z == 1) ? p1 : (z == 2) ? p2 : p3;
    float4*       out = (z == 0) ? d0 : (z == 1) ? d1 : (z == 2) ? d2 : d3;
    int i = blockIdx.x * 256 + threadIdx.x;
    if (i < n4) {
        float4 v = in[i];
        out[i] = make_float4(to_tf32(v.x), to_tf32(v.y), to_tf32(v.z), to_tf32(v.w));
    }
}
__global__ __launch_bounds__(256)
void conv_tf32(const float4* __restrict__ in, float4* __restrict__ out, int n4)
{
    int i = blockIdx.x * 256 + threadIdx.x;
    if (i < n4) {
        float4 v = in[i];
        out[i] = make_float4(to_tf32(v.x), to_tf32(v.y), to_tf32(v.z), to_tf32(v.w));
    }
}

// ---------------------------------------------------------------------------
// QKV projection, fused over blockIdx.z (0=Q, 1=K, 2=V).
// C[128,128] tile, BK=32, 2-stage cp.async (73.7 KB -> 3 CTAs/SM),
// stride-36 smem, warps 2m x 4n.
// ---------------------------------------------------------------------------
__global__ __launch_bounds__(256)
void proj_qkv(const float* __restrict__ bq, const float* __restrict__ bk,
              const float* __restrict__ bv, float* __restrict__ Qout,
              float* __restrict__ Kout)
{
    extern __shared__ float sm[];
    const uint32_t smb = smem_u32(sm);
    constexpr int STG = 2 * 128 * 36;

    const int tid = threadIdx.x, lane = tid & 31, wid = tid >> 5;
    const int g4 = lane >> 2, cq = lane & 3;
    const int wm = (wid & 1) * 64, wn = (wid >> 1) * 32;
    const int z = blockIdx.z;

    const float* Ag = g_Xr[z];
    const float* Bg = (z == 0) ? g_Wq : (z == 1) ? g_Wk : g_Wv;
    const float* bias = (z == 0) ? bq : (z == 1) ? bk : bv;

    const float* Arow = Ag + (size_t)(blockIdx.y * 128) * 1024;
    const float* Brow = Bg + (size_t)(blockIdx.x * 128) * 1024;

    auto loadAB = [&](int t, int s) {
        const uint32_t base = smb + (uint32_t)s * STG * 4;
        const int k0 = t * 32;
#pragma unroll
        for (int i = 0; i < 4; ++i) {
            int idx = tid + i * 256;
            int r = idx >> 3, seg = idx & 7;
            CP_A16(base + (uint32_t)(r * 36 + seg * 4) * 4,
                   Arow + (size_t)r * 1024 + k0 + seg * 4);
        }
#pragma unroll
        for (int i = 0; i < 4; ++i) {
            int idx = tid + i * 256;
            int r = idx >> 3, seg = idx & 7;
            CP_A16(base + (uint32_t)(128 * 36 + r * 36 + seg * 4) * 4,
                   Brow + (size_t)r * 1024 + k0 + seg * 4);
        }
    };

    float acc[4][4][4] = {};

    loadAB(0, 0); CP_COMMIT();

    for (int t = 0; t < 32; ++t) {
        if (t + 1 < 32) { loadAB(t + 1, (t + 1) & 1); CP_COMMIT(); }
        if (t + 1 < 32) { CP_WAIT1(); } else { CP_WAIT0(); }
        __syncthreads();

        const float* As = sm + (t & 1) * STG;
        const float* Bs = As + 128 * 36;
#pragma unroll
        for (int ks = 0; ks < 4; ++ks) {
            uint32_t afr[4][4], bfr[4][2];
#pragma unroll
            for (int m = 0; m < 4; ++m) {
                const float* p = As + (wm + m * 16 + g4) * 36 + ks * 8 + cq;
                afr[m][0] = __float_as_uint(p[0]);
                afr[m][1] = __float_as_uint(p[8 * 36]);
                afr[m][2] = __float_as_uint(p[4]);
                afr[m][3] = __float_as_uint(p[8 * 36 + 4]);
            }
#pragma unroll
            for (int n = 0; n < 4; ++n) {
                const float* p = Bs + (wn + n * 8 + g4) * 36 + ks * 8 + cq;
                bfr[n][0] = __float_as_uint(p[0]);
                bfr[n][1] = __float_as_uint(p[4]);
            }
#pragma unroll
            for (int m = 0; m < 4; ++m)
#pragma unroll
                for (int n = 0; n < 4; ++n)
                    mma_tf32(acc[m][n], afr[m], bfr[n]);
        }
        __syncthreads();   // protect buf (t&1)^1 before next iteration's load
    }

    float* OUT = (z == 0) ? Qout : Kout;
#pragma unroll
    for (int m = 0; m < 4; ++m) {
#pragma unroll
        for (int n = 0; n < 4; ++n) {
            const int col = wn + n * 8 + cq * 2;
#pragma unroll
            for (int h2 = 0; h2 < 2; ++h2) {
                const int row = wm + m * 16 + g4 + h2 * 8;
                const float c0 = acc[m][n][h2 * 2 + 0];
                const float c1 = acc[m][n][h2 * 2 + 1];
                const int mg = blockIdx.y * 128 + row;
                const int ng = blockIdx.x * 128 + col;
                const int bb = mg / 768, l = mg - bb * 768;
                const int hh = ng >> 6, dd = ng & 63;
                if (z < 2) {
                    float* dst = OUT + (((size_t)(bb * 16 + hh) * 768) + l) * 64 + dd;
                    dst[0] = to_tf32(c0 + bias[ng]);
                    dst[1] = to_tf32(c1 + bias[ng + 1]);
                } else {
                    g_Vt[((size_t)(bb * 16 + hh) * 64 + dd    ) * 768 + l] = to_tf32(c0 + bias[ng]);
                    g_Vt[((size_t)(bb * 16 + hh) * 64 + dd + 1) * 768 + l] = to_tf32(c1 + bias[ng + 1]);
                }
            }
        }
    }
}

// ---------------------------------------------------------------------------
// Output projection: same 2-stage structure, plain fp32 OUT.
// ---------------------------------------------------------------------------
__global__ __launch_bounds__(256)
void proj_out(const float* __restrict__ bias, float* __restrict__ OUT)
{
    extern __shared__ float sm[];
    const uint32_t smb = smem_u32(sm);
    constexpr int STG = 2 * 128 * 36;

    const int tid = threadIdx.x, lane = tid & 31, wid = tid >> 5;
    const int g4 = lane >> 2, cq = lane & 3;
    const int wm = (wid & 1) * 64, wn = (wid >> 1) * 32;

    const float* Arow = g_O2 + (size_t)(blockIdx.y * 128) * 1024;
    const float* Brow = g_Wo + (size_t)(blockIdx.x * 128) * 1024;

    auto loadAB = [&](int t, int s) {
        const uint32_t base = smb + (uint32_t)s * STG * 4;
        const int k0 = t * 32;
#pragma unroll
        for (int i = 0; i < 4; ++i) {
            int idx = tid + i * 256;
            int r = idx >> 3, seg = idx & 7;
            CP_A16(base + (uint32_t)(r * 36 + seg * 4) * 4,
                   Arow + (size_t)r * 1024 + k0 + seg * 4);
        }
#pragma unroll
        for (int i = 0; i < 4; ++i) {
            int idx = tid + i * 256;
            int r = idx >> 3, seg = idx & 7;
            CP_A16(base + (uint32_t)(128 * 36 + r * 36 + seg * 4) * 4,
                   Brow + (size_t)r * 1024 + k0 + seg * 4);
        }
    };

    float acc[4][4][4] = {};

    loadAB(0, 0); CP_COMMIT();

    for (int t = 0; t < 32; ++t) {
        if (t + 1 < 32) { loadAB(t + 1, (t + 1) & 1); CP_COMMIT(); }
        if (t + 1 < 32) { CP_WAIT1(); } else { CP_WAIT0(); }
        __syncthreads();

        const float* As = sm + (t & 1) * STG;
        const float* Bs = As + 128 * 36;
#pragma unroll
        for (int ks = 0; ks < 4; ++ks) {
            uint32_t afr[4][4], bfr[4][2];
#pragma unroll
            for (int m = 0; m < 4; ++m) {
                const float* p = As + (wm + m * 16 + g4) * 36 + ks * 8 + cq;
                afr[m][0] = __float_as_uint(p[0]);
                afr[m][1] = __float_as_uint(p[8 * 36]);
                afr[m][2] = __float_as_uint(p[4]);
                afr[m][3] = __float_as_uint(p[8 * 36 + 4]);
            }
#pragma unroll
            for (int n = 0; n < 4; ++n) {
                const float* p = Bs + (wn + n * 8 + g4) * 36 + ks * 8 + cq;
                bfr[n][0] = __float_as_uint(p[0]);
                bfr[n][1] = __float_as_uint(p[4]);
            }
#pragma unroll
            for (int m = 0; m < 4; ++m)
#pragma unroll
                for (int n = 0; n < 4; ++n)
                    mma_tf32(acc[m][n], afr[m], bfr[n]);
        }
        __syncthreads();
    }

#pragma unroll
    for (int m = 0; m < 4; ++m) {
#pragma unroll
        for (int n = 0; n < 4; ++n) {
            const int col = wn + n * 8 + cq * 2;
#pragma unroll
            for (int h2 = 0; h2 < 2; ++h2) {
                const int row = wm + m * 16 + g4 + h2 * 8;
                const int mg = blockIdx.y * 128 + row;
                const int ng = blockIdx.x * 128 + col;
                float* dst = OUT + (size_t)mg * 1024 + ng;
                dst[0] = acc[m][n][h2 * 2 + 0] + bias[ng];
                dst[1] = acc[m][n][h2 * 2 + 1] + bias[ng + 1];
            }
        }
    }
}

// ---------------------------------------------------------------------------
// Fused scores + rel + exp + rowsum (R7-proven). One CTA per (qt, bh).
// ---------------------------------------------------------------------------
__global__ __launch_bounds__(256)
void scores_fused()
{
    extern __shared__ float sm[];
    float* Bbuf = sm;                       // [2][128*68]
    float* Wbuf = sm + 2 * 128 * 68;        // [2][128*132]
    const uint32_t bb_a = smem_u32(Bbuf);
    const uint32_t wq_a = smem_u32(Wbuf);
    __shared__ float ssum[128];

    const int tid  = threadIdx.x;
    const int lane = tid & 31, wid = tid >> 5;
    const int g4 = lane >> 2, cq = lane & 3;
    const int wm = (wid & 3) * 32, wn = (wid >> 2) * 64;
    const int qt = blockIdx.x, bh = blockIdx.y;

    if (tid < 128) ssum[tid] = 0.f;

    const float* Qg = g_Qp + ((size_t)bh * 768 + qt * 128) * 64;
    const float* Kg = g_Kp + (size_t)bh * 768 * 64;
    const int base0 = 640 - qt * 128;

#pragma unroll
    for (int i = 0; i < 8; ++i) {
        int idx = tid + i * 256;
        int r = idx >> 4, seg = idx & 15;
        CP_A16(wq_a + (uint32_t)(r * 68 + seg * 4) * 4, Qg + r * 64 + seg * 4);
    }
    CP_COMMIT();

    auto loadB = [&](int i) {
        const uint32_t base = bb_a + (uint32_t)(i & 1) * (128 * 68 * 4);
        const bool content = (i >= 2) && ((i & 1) == 0);
        if (content) {
            const int xt = (i - 2) >> 1;
            const float* s0 = Kg + (size_t)xt * 128 * 64;
#pragma unroll
            for (int k = 0; k < 8; ++k) {
                int idx = tid + k * 256;
                int r = idx >> 4, seg = idx & 15;
                CP_A16(base + (uint32_t)(r * 68 + seg * 4) * 4, s0 + r * 64 + seg * 4);
            }
        } else {
            const int w = (i < 2) ? i : ((i + 1) >> 1);
            const int jb = base0 + w * 128;
#pragma unroll
            for (int k = 0; k < 8; ++k) {
                int idx = tid + k * 256;
                int r = idx >> 4, seg = idx & 15;
                int j = jb + r;
                int jc = (j > 1534) ? 1534 : j;
                unsigned sz = (j <= 1534) ? 16u : 0u;
                CP_A16Z(base + (uint32_t)(r * 68 + seg * 4) * 4,
                        g_Ec + (size_t)jc * 64 + seg * 4, sz);
            }
        }
    };

    loadB(0); CP_COMMIT();
    loadB(1); CP_COMMIT();

    CP_WAIT2();
    __syncthreads();

    uint32_t afr[8][2][4];
#pragma unroll
    for (int ks = 0; ks < 8; ++ks)
#pragma unroll
        for (int mt = 0; mt < 2; ++mt) {
            const float* q = Wbuf + (wm + mt * 16 + g4) * 68 + ks * 8 + cq;
            afr[ks][mt][0] = __float_as_uint(q[0]);
            afr[ks][mt][1] = __float_as_uint(q[8 * 68]);
            afr[ks][mt][2] = __float_as_uint(q[4]);
            afr[ks][mt][3] = __float_as_uint(q[8 * 68 + 4]);
        }
    __syncthreads();

    CP_WAIT1();
    __syncthreads();

    float rsum[4] = {0.f, 0.f, 0.f, 0.f};

#pragma unroll 1
    for (int i = 0; i < 13; ++i) {
        const float* Bsb = Bbuf + (i & 1) * (128 * 68);
        float acc[2][8][4] = {};

#pragma unroll
        for (int ks = 0; ks < 8; ++ks) {
            uint32_t bfr[8][2];
#pragma unroll
            for (int nt = 0; nt < 8; ++nt) {
                const float* b = Bsb + (wn + nt * 8 + g4) * 68 + ks * 8 + cq;
                bfr[nt][0] = __float_as_uint(b[0]);
                bfr[nt][1] = __float_as_uint(b[4]);
            }
#pragma unroll
            for (int mt = 0; mt < 2; ++mt)
#pragma unroll
                for (int nt = 0; nt < 8; ++nt)
                    mma_tf32(acc[mt][nt], afr[ks][mt], bfr[nt]);
        }

        const bool content = (i >= 2) && ((i & 1) == 0);
        if (!content) {
            const int w = (i < 2) ? i : ((i + 1) >> 1);
            float* Wd = Wbuf + (w & 1) * (128 * 132);
#pragma unroll
            for (int mt = 0; mt < 2; ++mt)
#pragma unroll
                for (int h2 = 0; h2 < 2; ++h2) {
                    const int row = wm + mt * 16 + g4 + h2 * 8;
#pragma unroll
                    for (int nt = 0; nt < 8; ++nt) {
                        const int col = wn + nt * 8 + 2 * cq;
                        Wd[row * 132 + col    ] = acc[mt][nt][h2 * 2 + 0];
                        Wd[row * 132 + col + 1] = acc[mt][nt][h2 * 2 + 1];
                    }
                }
        } else {
            const int xt = (i - 2) >> 1;
            const float* W0 = Wbuf + (xt & 1) * (128 * 132);
            const float* W1 = Wbuf + ((xt + 1) & 1) * (128 * 132);
            float* Sd = g_S + ((size_t)bh * 768 + qt * 128) * 768 + xt * 128;
#pragma unroll
            for (int mt = 0; mt < 2; ++mt)
#pragma unroll
                for (int h2 = 0; h2 < 2; ++h2) {
                    const int row = wm + mt * 16 + g4 + h2 * 8;
                    float rs = 0.f;
#pragma unroll
                    for (int nt = 0; nt < 8; ++nt) {
                        const int col = wn + nt * 8 + 2 * cq;
                        const int c0 = col - row + 127;
                        const int c1 = c0 + 1;
                        const float r0 = (c0 < 128) ? W0[row * 132 + c0]
                                                    : W1[row * 132 + c0 - 128];
                        const float r1 = (c1 < 128) ? W0[row * 132 + c1]
                                                    : W1[row * 132 + c1 - 128];
                        const float p0 = __expf(SCALE * (acc[mt][nt][h2 * 2 + 0] + r0));
                        const float p1 = __expf(SCALE * (acc[mt][nt][h2 * 2 + 1] + r1));
                        rs += p0 + p1;
                        *(float2*)&Sd[(size_t)row * 768 + col] =
                            make_float2(to_tf32(p0), to_tf32(p1));
                    }
                    rsum[mt * 2 + h2] += rs;
                }
        }

        __syncthreads();
        if (i + 2 < 13) { loadB(i + 2); CP_COMMIT(); }
        if (i + 1 < 13) {
            if (i + 2 < 13) { CP_WAIT1(); } else { CP_WAIT0(); }
            __syncthreads();
        }
    }

#pragma unroll
    for (int k = 0; k < 4; ++k) {
        rsum[k] += __shfl_xor_sync(0xffffffffu, rsum[k], 1);
        rsum[k] += __shfl_xor_sync(0xffffffffu, rsum[k], 2);
    }
    __syncthreads();
    if (cq == 0) {
#pragma unroll
        for (int k = 0; k < 4; ++k) {
            const int row = wm + (k >> 1) * 16 + g4 + (k & 1) * 8;
            atomicAdd(&ssum[row], rsum[k]);
        }
    }
    __syncthreads();
    if (tid < 128)
        g_InvSum[bh * 768 + qt * 128 + tid] = 1.0f / ssum[tid];
}

// ---------------------------------------------------------------------------
// AV GEMM (R6-proven): C[128,64] = P @ Vt^T per (qt,bh); epilogue normalize.
// ---------------------------------------------------------------------------
__global__ __launch_bounds__(256)
void av_mma()
{
    extern __shared__ float sm[];
    constexpr int ASZ = 128 * 68, BSZ = 64 * 68, STG = ASZ + BSZ;
    const uint32_t smb = smem_u32(sm);

    const int tid = threadIdx.x, lane = tid & 31, wid = tid >> 5;
    const int g4 = lane >> 2, cq = lane & 3;
    const int wm = (wid & 3) * 32, wn = (wid >> 2) * 32;
    const int qt = blockIdx.x, bh = blockIdx.y;

    const float* P = g_S  + ((size_t)bh * 768 + qt * 128) * 768;
    const float* V = g_Vt + (size_t)bh * 64 * 768;

    auto load = [&](int t, int s) {
        const uint32_t base = smb + (uint32_t)s * STG * 4;
        const int k0 = t * 64;
#pragma unroll
        for (int i = 0; i < 8; ++i) {
            int idx = tid + i * 256;
            int r = idx >> 4, seg = idx & 15;
            CP_A16(base + (uint32_t)(r * 68 + seg * 4) * 4,
                   P + (size_t)r * 768 + k0 + seg * 4);
        }
#pragma unroll
        for (int i = 0; i < 4; ++i) {
            int idx = tid + i * 256;
            int r = idx >> 4, seg = idx & 15;
            CP_A16(base + (uint32_t)(ASZ + r * 68 + seg * 4) * 4,
                   V + (size_t)r * 768 + k0 + seg * 4);
        }
    };

    float acc[2][4][4] = {};

    load(0, 0); CP_COMMIT();
    load(1, 1); CP_COMMIT();
    CP_WAIT1();
    __syncthreads();

#pragma unroll 1
    for (int t = 0; t < 12; ++t) {
        const float* As = sm + (t & 1) * STG;
        const float* Bs = As + ASZ;
#pragma unroll
        for (int ks = 0; ks < 8; ++ks) {
            uint32_t afr[2][4], bfr[4][2];
#pragma unroll
            for (int mt = 0; mt < 2; ++mt) {
                const float* p = As + (wm + mt * 16 + g4) * 68 + ks * 8 + cq;
                afr[mt][0] = __float_as_uint(p[0]);
                afr[mt][1] = __float_as_uint(p[8 * 68]);
                afr[mt][2] = __float_as_uint(p[4]);
                afr[mt][3] = __float_as_uint(p[8 * 68 + 4]);
            }
#pragma unroll
            for (int nt = 0; nt < 4; ++nt) {
                const float* p = Bs + (wn + nt * 8 + g4) * 68 + ks * 8 + cq;
                bfr[nt][0] = __float_as_uint(p[0]);
                bfr[nt][1] = __float_as_uint(p[4]);
            }
#pragma unroll
            for (int mt = 0; mt < 2; ++mt)
#pragma unroll
                for (int nt = 0; nt < 4; ++nt)
                    mma_tf32(acc[mt][nt], afr[mt], bfr[nt]);
        }
        __syncthreads();
        if (t + 2 < 12) { load(t + 2, t & 1); CP_COMMIT(); }
        if (t + 1 < 12) {
            if (t + 2 < 12) { CP_WAIT1(); } else { CP_WAIT0(); }
            __syncthreads();
        }
    }

    const int b = bh >> 4, h = bh & 15;
#pragma unroll
    for (int mt = 0; mt < 2; ++mt)
#pragma unroll
        for (int h2 = 0; h2 < 2; ++h2) {
            const int row = wm + mt * 16 + g4 + h2 * 8;
            const float inv = g_InvSum[bh * 768 + qt * 128 + row];
#pragma unroll
            for (int nt = 0; nt < 4; ++nt) {
                const int col = wn + nt * 8 + 2 * cq;
                *(float2*)&g_O2[((size_t)(b * 768) + qt * 128 + row) * 1024
                                + h * 64 + col] =
                    make_float2(to_tf32(acc[mt][nt][h2 * 2 + 0] * inv),
                                to_tf32(acc[mt][nt][h2 * 2 + 1] * inv));
            }
        }
}

// ---------------------------------------------------------------------------
extern "C" void kernel_launch(void* const* d_in, const int* in_sizes, int n_in,
                              void* d_out, int out_size)
{
    const float* query = (const float*)d_in[0];
    const float* key   = (const float*)d_in[1];
    const float* value = (const float*)d_in[2];
    const float* w_q   = (const float*)d_in[3];
    const float* b_q   = (const float*)d_in[4];
    const float* w_k   = (const float*)d_in[5];
    const float* b_k   = (const float*)d_in[6];
    const float* w_v   = (const float*)d_in[7];
    const float* b_v   = (const float*)d_in[8];
    const float* w_o   = (const float*)d_in[9];
    const float* b_o   = (const float*)d_in[10];
    const float* relE  = (const float*)d_in[11];
    float* out = (float*)d_out;

    float *xr, *wq, *wk, *wv, *wo, *qp, *kp, *ec;
    cudaGetSymbolAddress((void**)&xr, g_Xr);
    cudaGetSymbolAddress((void**)&wq, g_Wq);
    cudaGetSymbolAddress((void**)&wk, g_Wk);
    cudaGetSymbolAddress((void**)&wv, g_Wv);
    cudaGetSymbolAddress((void**)&wo, g_Wo);
    cudaGetSymbolAddress((void**)&qp, g_Qp);
    cudaGetSymbolAddress((void**)&kp, g_Kp);
    cudaGetSymbolAddress((void**)&ec, g_Ec);

    const int SMEMP   = 2 * 2 * 128 * 36 * 4;                    // 73728
    const int SC_SMEM = (2 * 128 * 68 + 2 * 128 * 132) * 4;      // 204800
    const int AV_SMEM = 2 * (128 * 68 + 64 * 68) * 4;            // 104448
    cudaFuncSetAttribute(proj_qkv, cudaFuncAttributeMaxDynamicSharedMemorySize, SMEMP);
    cudaFuncSetAttribute(proj_out, cudaFuncAttributeMaxDynamicSharedMemorySize, SMEMP);
    cudaFuncSetAttribute(scores_fused, cudaFuncAttributeMaxDynamicSharedMemorySize, SC_SMEM);
    cudaFuncSetAttribute(av_mma,       cudaFuncAttributeMaxDynamicSharedMemorySize, AV_SMEM);

    const int NW4 = 1024 * 1024 / 4;
    const int NX4 = M_ * D_ / 4;

    // weights (4-way z-batched) + rel embedding
    conv_tf32_z<<<dim3((NW4 + 255) / 256, 1, 4), 256>>>(
        (const float4*)w_q, (const float4*)w_k, (const float4*)w_v, (const float4*)w_o,
        (float4*)wq, (float4*)wk, (float4*)wv, (float4*)wo, NW4);
    conv_tf32<<<(1535 * 64 / 4 + 255) / 256, 256>>>(
        (const float4*)relE, (float4*)ec, 1535 * 64 / 4);

    // inputs (3-way z-batched into g_Xr[0..2])
    conv_tf32_z<<<dim3((NX4 + 255) / 256, 1, 3), 256>>>(
        (const float4*)query, (const float4*)key, (const float4*)value,
        (const float4*)query,
        (float4*)(xr), (float4*)(xr + M_ * D_), (float4*)(xr + 2 * M_ * D_),
        (float4*)(xr), NX4);

    // fused QKV projection: one launch, 3 full projections
    proj_qkv<<<dim3(8, 48, 3), 256, SMEMP>>>(b_q, b_k, b_v, qp, kp);

    scores_fused<<<dim3(6, 128), 256, SC_SMEM>>>();
    av_mma<<<dim3(6, 128), 256, AV_SMEM>>>();

    proj_out<<<dim3(8, 48), 256, SMEMP>>>(b_o, out);
}